// round 2
// baseline (speedup 1.0000x reference)
#include <cuda_runtime.h>
#include <cuda_bf16.h>
#include <cstdint>

// Problem constants (fixed by the dataset)
#define N_NODES 50000
#define E_EDGES 625000
#define HIDDEN  128

// ---------------- scratch (no allocs allowed -> __device__ globals) ----------
__device__ float g_sum[N_NODES * HIDDEN];        // 25.6 MB  segment sums
__device__ int   g_count[N_NODES];               // per-node edge counts
__device__ int   g_offset[N_NODES];              // CSR offsets
__device__ int   g_cursor[N_NODES];              // fill cursors
__device__ int   g_edge_ids[E_EDGES];            // CSR edge id list

// ---------------- 1. zero counts --------------------------------------------
__global__ void zero_counts_kernel() {
    int i = blockIdx.x * blockDim.x + threadIdx.x;
    if (i < N_NODES) g_count[i] = 0;
}

// ---------------- 2. histogram of rows ---------------------------------------
// edge_index arrives as int32 (harness downcasts int64). Row = first E elems.
__global__ void hist_kernel(const int* __restrict__ edge_row) {
    int e = blockIdx.x * blockDim.x + threadIdx.x;
    if (e < E_EDGES) {
        int r = edge_row[e];
        atomicAdd(&g_count[r], 1);
    }
}

// ---------------- 3. exclusive scan (single block, 1024 threads) -------------
__global__ void scan_kernel() {
    __shared__ int s[1024];
    const int t = threadIdx.x;
    const int CHUNK = (N_NODES + 1023) / 1024;   // 49
    int base = t * CHUNK;
    int sum = 0;
    for (int i = 0; i < CHUNK; i++) {
        int idx = base + i;
        if (idx < N_NODES) sum += g_count[idx];
    }
    s[t] = sum;
    __syncthreads();
    // Hillis-Steele inclusive scan
    for (int off = 1; off < 1024; off <<= 1) {
        int v = 0;
        if (t >= off) v = s[t - off];
        __syncthreads();
        if (t >= off) s[t] += v;
        __syncthreads();
    }
    int run = (t == 0) ? 0 : s[t - 1];
    for (int i = 0; i < CHUNK; i++) {
        int idx = base + i;
        if (idx < N_NODES) {
            g_offset[idx] = run;
            g_cursor[idx] = run;
            run += g_count[idx];
        }
    }
}

// ---------------- 4. fill CSR edge id list -----------------------------------
__global__ void fill_kernel(const int* __restrict__ edge_row) {
    int e = blockIdx.x * blockDim.x + threadIdx.x;
    if (e < E_EDGES) {
        int r = edge_row[e];
        int pos = atomicAdd(&g_cursor[r], 1);
        g_edge_ids[pos] = e;
    }
}

// ---------------- 5. gather segment-sum: one warp per node -------------------
__global__ void gather_kernel(const float* __restrict__ edge_attr) {
    int gtid = blockIdx.x * blockDim.x + threadIdx.x;
    int warp = gtid >> 5;
    int lane = gtid & 31;
    if (warp >= N_NODES) return;

    int start = g_offset[warp];
    int cnt   = g_count[warp];

    float4 acc = make_float4(0.f, 0.f, 0.f, 0.f);
    const float4* ea4 = (const float4*)edge_attr;
    for (int i = 0; i < cnt; i++) {
        int e = g_edge_ids[start + i];
        float4 v = ea4[(size_t)e * 32 + lane];   // 128 floats = 32 lanes x float4
        acc.x += v.x; acc.y += v.y; acc.z += v.z; acc.w += v.w;
    }
    ((float4*)g_sum)[(size_t)warp * 32 + lane] = acc;
}

// ---------------- 6. fused 2-layer MLP + residual ----------------------------
// Persistent kernel: weights staged in smem once per CTA; tile of 16 nodes.
// Thread layout: n = tid>>4 (node in tile, 0..15), j0 = (tid&15)*8 (8 cols).
#define TILE_N   16
#define IN_STR   260   // 256 + pad (keeps float4 alignment: 260*4 % 16 == 0)
#define HID_STR  132   // 128 + pad
#define NUM_TILES (N_NODES / TILE_N)   // 3125, exact

__global__ __launch_bounds__(256, 1)
void mlp_kernel(const float* __restrict__ x,
                const float* __restrict__ W1, const float* __restrict__ b1,
                const float* __restrict__ W2, const float* __restrict__ b2,
                float* __restrict__ out) {
    extern __shared__ float smem[];
    float* W1s  = smem;                  // 256*128 = 32768
    float* W2s  = W1s + 32768;           // 128*128 = 16384
    float* b1s  = W2s + 16384;           // 128
    float* b2s  = b1s + 128;             // 128
    float* in_s = b2s + 128;             // TILE_N * IN_STR  = 4160
    float* hid_s= in_s + TILE_N * IN_STR;// TILE_N * HID_STR = 2112

    const int tid = threadIdx.x;

    // --- stage weights/biases (coalesced float4) ---
    {
        const float4* W1v = (const float4*)W1;
        float4* W1sv = (float4*)W1s;
        for (int i = tid; i < 32768 / 4; i += 256) W1sv[i] = W1v[i];
        const float4* W2v = (const float4*)W2;
        float4* W2sv = (float4*)W2s;
        for (int i = tid; i < 16384 / 4; i += 256) W2sv[i] = W2v[i];
        if (tid < 128) { b1s[tid] = b1[tid]; b2s[tid] = b2[tid]; }
    }

    const int n  = tid >> 4;         // 0..15
    const int j0 = (tid & 15) * 8;   // 0..120 step 8

    for (int tile = blockIdx.x; tile < NUM_TILES; tile += gridDim.x) {
        __syncthreads();   // protect in_s/hid_s from previous iteration readers

        // --- fill in_s: [TILE_N][256] = [x | g_sum], 1024 float4 loads ---
        {
            const float4* xv = (const float4*)x;
            const float4* sv = (const float4*)g_sum;
            #pragma unroll
            for (int i = 0; i < 4; i++) {
                int idx  = tid + i * 256;       // 0..1023
                int node = idx >> 6;            // 64 float4 per node
                int f    = idx & 63;
                int gnode = tile * TILE_N + node;
                float4 v = (f < 32) ? xv[(size_t)gnode * 32 + f]
                                    : sv[(size_t)gnode * 32 + (f - 32)];
                *(float4*)&in_s[node * IN_STR + f * 4] = v;
            }
        }
        __syncthreads();

        // --- layer 1: [16,256] x [256,128] + b1, relu ---
        float a0 = b1s[j0 + 0], a1 = b1s[j0 + 1], a2 = b1s[j0 + 2], a3 = b1s[j0 + 3];
        float a4 = b1s[j0 + 4], a5 = b1s[j0 + 5], a6 = b1s[j0 + 6], a7 = b1s[j0 + 7];
        const float* inrow = &in_s[n * IN_STR];
        #pragma unroll 8
        for (int k = 0; k < 256; k++) {
            float v = inrow[k];
            float4 wA = *(const float4*)&W1s[k * 128 + j0];
            float4 wB = *(const float4*)&W1s[k * 128 + j0 + 4];
            a0 += v * wA.x; a1 += v * wA.y; a2 += v * wA.z; a3 += v * wA.w;
            a4 += v * wB.x; a5 += v * wB.y; a6 += v * wB.z; a7 += v * wB.w;
        }
        a0 = fmaxf(a0, 0.f); a1 = fmaxf(a1, 0.f); a2 = fmaxf(a2, 0.f); a3 = fmaxf(a3, 0.f);
        a4 = fmaxf(a4, 0.f); a5 = fmaxf(a5, 0.f); a6 = fmaxf(a6, 0.f); a7 = fmaxf(a7, 0.f);
        *(float4*)&hid_s[n * HID_STR + j0]     = make_float4(a0, a1, a2, a3);
        *(float4*)&hid_s[n * HID_STR + j0 + 4] = make_float4(a4, a5, a6, a7);
        __syncthreads();

        // --- layer 2: [16,128] x [128,128] + b2 + residual ---
        float c0 = b2s[j0 + 0], c1 = b2s[j0 + 1], c2 = b2s[j0 + 2], c3 = b2s[j0 + 3];
        float c4 = b2s[j0 + 4], c5 = b2s[j0 + 5], c6 = b2s[j0 + 6], c7 = b2s[j0 + 7];
        const float* hrow = &hid_s[n * HID_STR];
        #pragma unroll 8
        for (int k = 0; k < 128; k++) {
            float v = hrow[k];
            float4 wA = *(const float4*)&W2s[k * 128 + j0];
            float4 wB = *(const float4*)&W2s[k * 128 + j0 + 4];
            c0 += v * wA.x; c1 += v * wA.y; c2 += v * wA.z; c3 += v * wA.w;
            c4 += v * wB.x; c5 += v * wB.y; c6 += v * wB.z; c7 += v * wB.w;
        }
        // residual: x values still live in in_s[n][0..127]
        int gnode = tile * TILE_N + n;
        float4 r0 = make_float4(c0 + inrow[j0 + 0], c1 + inrow[j0 + 1],
                                c2 + inrow[j0 + 2], c3 + inrow[j0 + 3]);
        float4 r1 = make_float4(c4 + inrow[j0 + 4], c5 + inrow[j0 + 5],
                                c6 + inrow[j0 + 6], c7 + inrow[j0 + 7]);
        *(float4*)&out[(size_t)gnode * 128 + j0]     = r0;
        *(float4*)&out[(size_t)gnode * 128 + j0 + 4] = r1;
    }
}

// ---------------- launcher ---------------------------------------------------
extern "C" void kernel_launch(void* const* d_in, const int* in_sizes, int n_in,
                              void* d_out, int out_size) {
    const float* x          = (const float*)d_in[0];
    const int*   edge_row   = (const int*)d_in[1];    // int64 -> int32 by harness; first E = row
    const float* edge_attr  = (const float*)d_in[2];
    // d_in[3] = u (unused), d_in[4] = batch (unused)
    const float* W1         = (const float*)d_in[5];
    const float* b1         = (const float*)d_in[6];
    const float* W2         = (const float*)d_in[7];
    const float* b2         = (const float*)d_in[8];
    float*       out        = (float*)d_out;

    // 1. zero counts
    zero_counts_kernel<<<(N_NODES + 255) / 256, 256>>>();
    // 2. histogram
    hist_kernel<<<(E_EDGES + 255) / 256, 256>>>(edge_row);
    // 3. scan -> offsets & cursors
    scan_kernel<<<1, 1024>>>();
    // 4. CSR fill
    fill_kernel<<<(E_EDGES + 255) / 256, 256>>>(edge_row);
    // 5. gather segment-sum (warp per node)
    {
        int threads = 256;
        int blocks = (N_NODES * 32 + threads - 1) / threads;
        gather_kernel<<<blocks, threads>>>(edge_attr);
    }
    // 6. fused MLP + residual (persistent)
    {
        size_t smem_bytes = (32768 + 16384 + 128 + 128 +
                             TILE_N * IN_STR + TILE_N * HID_STR) * sizeof(float);
        cudaFuncSetAttribute(mlp_kernel, cudaFuncAttributeMaxDynamicSharedMemorySize,
                             (int)smem_bytes);
        mlp_kernel<<<148, 256, smem_bytes>>>(x, W1, b1, W2, b2, out);
    }
}

// round 3
// speedup vs baseline: 2.1965x; 2.1965x over previous
#include <cuda_runtime.h>
#include <cuda_bf16.h>
#include <cstdint>

#define N_NODES 50000
#define E_EDGES 625000
#define HIDDEN  128

// ---------------- scratch ----------------------------------------------------
__device__ float g_sum[N_NODES * HIDDEN];        // segment sums
__device__ int   g_count[N_NODES];
__device__ int   g_offset[N_NODES];
__device__ int   g_cursor[N_NODES];
__device__ int   g_edge_ids[E_EDGES];

// ---------------- 1. zero counts ---------------------------------------------
__global__ void zero_counts_kernel() {
    int i = blockIdx.x * blockDim.x + threadIdx.x;
    if (i < N_NODES) g_count[i] = 0;
}

// ---------------- 2. histogram (edge_index arrives int32; first E = row) -----
__global__ void hist_kernel(const int* __restrict__ edge_row) {
    int e = blockIdx.x * blockDim.x + threadIdx.x;
    if (e < E_EDGES) atomicAdd(&g_count[edge_row[e]], 1);
}

// ---------------- 3. exclusive scan ------------------------------------------
__global__ void scan_kernel() {
    __shared__ int s[1024];
    const int t = threadIdx.x;
    const int CHUNK = (N_NODES + 1023) / 1024;   // 49
    int base = t * CHUNK;
    int sum = 0;
    for (int i = 0; i < CHUNK; i++) {
        int idx = base + i;
        if (idx < N_NODES) sum += g_count[idx];
    }
    s[t] = sum;
    __syncthreads();
    for (int off = 1; off < 1024; off <<= 1) {
        int v = 0;
        if (t >= off) v = s[t - off];
        __syncthreads();
        if (t >= off) s[t] += v;
        __syncthreads();
    }
    int run = (t == 0) ? 0 : s[t - 1];
    for (int i = 0; i < CHUNK; i++) {
        int idx = base + i;
        if (idx < N_NODES) {
            g_offset[idx] = run;
            g_cursor[idx] = run;
            run += g_count[idx];
        }
    }
}

// ---------------- 4. CSR fill -------------------------------------------------
__global__ void fill_kernel(const int* __restrict__ edge_row) {
    int e = blockIdx.x * blockDim.x + threadIdx.x;
    if (e < E_EDGES) {
        int pos = atomicAdd(&g_cursor[edge_row[e]], 1);
        g_edge_ids[pos] = e;
    }
}

// ---------------- 5. gather segment-sum (warp per node, MLP=4) ---------------
__global__ void gather_kernel(const float* __restrict__ edge_attr) {
    int gtid = blockIdx.x * blockDim.x + threadIdx.x;
    int warp = gtid >> 5;
    int lane = gtid & 31;
    if (warp >= N_NODES) return;

    int start = g_offset[warp];
    int cnt   = g_count[warp];

    float4 acc = make_float4(0.f, 0.f, 0.f, 0.f);
    const float4* ea4 = (const float4*)edge_attr;

    int i = 0;
    for (; i + 4 <= cnt; i += 4) {
        // 4 independent id loads, then 4 independent payload loads -> MLP=4
        int e0 = g_edge_ids[start + i + 0];
        int e1 = g_edge_ids[start + i + 1];
        int e2 = g_edge_ids[start + i + 2];
        int e3 = g_edge_ids[start + i + 3];
        float4 v0 = ea4[(size_t)e0 * 32 + lane];
        float4 v1 = ea4[(size_t)e1 * 32 + lane];
        float4 v2 = ea4[(size_t)e2 * 32 + lane];
        float4 v3 = ea4[(size_t)e3 * 32 + lane];
        acc.x += v0.x + v1.x + v2.x + v3.x;
        acc.y += v0.y + v1.y + v2.y + v3.y;
        acc.z += v0.z + v1.z + v2.z + v3.z;
        acc.w += v0.w + v1.w + v2.w + v3.w;
    }
    for (; i < cnt; i++) {
        int e = g_edge_ids[start + i];
        float4 v = ea4[(size_t)e * 32 + lane];
        acc.x += v.x; acc.y += v.y; acc.z += v.z; acc.w += v.w;
    }
    ((float4*)g_sum)[(size_t)warp * 32 + lane] = acc;
}

// ---------------- 6. fused 2-layer MLP + residual ----------------------------
// Tile = 32 nodes. 256 threads: j0 = (tid&31)*4 (4 cols), nodes (tid>>5)*4..+3.
// W reads: contiguous 512B LDS.128 per warp per k (conflict-free).
// A reads: full-warp broadcast scalars.
// Hidden activations overwrite in_s[n][128..255] (g_sum half, dead after L1).
#define MT        32
#define NUM_TILES ((N_NODES + MT - 1) / MT)   // 1563

__global__ __launch_bounds__(256, 1)
void mlp_kernel(const float* __restrict__ x,
                const float* __restrict__ W1, const float* __restrict__ b1,
                const float* __restrict__ W2, const float* __restrict__ b2,
                float* __restrict__ out) {
    extern __shared__ float smem[];
    float* W1s  = smem;                   // 256*128 = 32768
    float* W2s  = W1s + 32768;            // 128*128 = 16384
    float* b1s  = W2s + 16384;            // 128
    float* b2s  = b1s + 128;              // 128
    float* in_s = b2s + 128;              // MT * 256 = 8192
    // total 57600 floats = 230400 B

    const int tid = threadIdx.x;

    // stage weights/biases
    {
        const float4* W1v = (const float4*)W1;
        float4* W1sv = (float4*)W1s;
        for (int i = tid; i < 32768 / 4; i += 256) W1sv[i] = W1v[i];
        const float4* W2v = (const float4*)W2;
        float4* W2sv = (float4*)W2s;
        for (int i = tid; i < 16384 / 4; i += 256) W2sv[i] = W2v[i];
        if (tid < 128) { b1s[tid] = b1[tid]; b2s[tid] = b2[tid]; }
    }

    const int j0 = (tid & 31) * 4;        // 4 output columns
    const int n0 = (tid >> 5) * 4;        // 4 local nodes (warp-uniform)

    const float4 bias1 = (tid < 256) ? make_float4(0,0,0,0) : make_float4(0,0,0,0); // placeholder avoided below

    for (int tile = blockIdx.x; tile < NUM_TILES; tile += gridDim.x) {
        __syncthreads();   // protect in_s from previous-iteration readers

        // ---- stage input tile: in_s[32][256] = [x | g_sum] ------------------
        {
            const float4* xv = (const float4*)x;
            const float4* sv = (const float4*)g_sum;
            #pragma unroll
            for (int i = 0; i < 8; i++) {
                int idx   = tid + i * 256;      // 0..2047
                int node  = idx >> 6;           // 64 float4 per node
                int f     = idx & 63;
                int gnode = tile * MT + node;
                float4 v;
                if (gnode < N_NODES) {
                    v = (f < 32) ? xv[(size_t)gnode * 32 + f]
                                 : sv[(size_t)gnode * 32 + (f - 32)];
                } else {
                    v = make_float4(0.f, 0.f, 0.f, 0.f);
                }
                *(float4*)&in_s[node * 256 + f * 4] = v;
            }
        }
        __syncthreads();

        // ---- layer 1: [32,256] x [256,128] + b1, relu -----------------------
        float4 b1v = *(const float4*)&b1s[j0];
        float acc[4][4];
        #pragma unroll
        for (int i = 0; i < 4; i++) {
            acc[i][0] = b1v.x; acc[i][1] = b1v.y; acc[i][2] = b1v.z; acc[i][3] = b1v.w;
        }
        #pragma unroll 4
        for (int k = 0; k < 256; k += 4) {
            float4 a0 = *(const float4*)&in_s[(n0 + 0) * 256 + k];
            float4 a1 = *(const float4*)&in_s[(n0 + 1) * 256 + k];
            float4 a2 = *(const float4*)&in_s[(n0 + 2) * 256 + k];
            float4 a3 = *(const float4*)&in_s[(n0 + 3) * 256 + k];
            {
                float4 w = *(const float4*)&W1s[(k + 0) * 128 + j0];
                acc[0][0] += a0.x * w.x; acc[0][1] += a0.x * w.y; acc[0][2] += a0.x * w.z; acc[0][3] += a0.x * w.w;
                acc[1][0] += a1.x * w.x; acc[1][1] += a1.x * w.y; acc[1][2] += a1.x * w.z; acc[1][3] += a1.x * w.w;
                acc[2][0] += a2.x * w.x; acc[2][1] += a2.x * w.y; acc[2][2] += a2.x * w.z; acc[2][3] += a2.x * w.w;
                acc[3][0] += a3.x * w.x; acc[3][1] += a3.x * w.y; acc[3][2] += a3.x * w.z; acc[3][3] += a3.x * w.w;
            }
            {
                float4 w = *(const float4*)&W1s[(k + 1) * 128 + j0];
                acc[0][0] += a0.y * w.x; acc[0][1] += a0.y * w.y; acc[0][2] += a0.y * w.z; acc[0][3] += a0.y * w.w;
                acc[1][0] += a1.y * w.x; acc[1][1] += a1.y * w.y; acc[1][2] += a1.y * w.z; acc[1][3] += a1.y * w.w;
                acc[2][0] += a2.y * w.x; acc[2][1] += a2.y * w.y; acc[2][2] += a2.y * w.z; acc[2][3] += a2.y * w.w;
                acc[3][0] += a3.y * w.x; acc[3][1] += a3.y * w.y; acc[3][2] += a3.y * w.z; acc[3][3] += a3.y * w.w;
            }
            {
                float4 w = *(const float4*)&W1s[(k + 2) * 128 + j0];
                acc[0][0] += a0.z * w.x; acc[0][1] += a0.z * w.y; acc[0][2] += a0.z * w.z; acc[0][3] += a0.z * w.w;
                acc[1][0] += a1.z * w.x; acc[1][1] += a1.z * w.y; acc[1][2] += a1.z * w.z; acc[1][3] += a1.z * w.w;
                acc[2][0] += a2.z * w.x; acc[2][1] += a2.z * w.y; acc[2][2] += a2.z * w.z; acc[2][3] += a2.z * w.w;
                acc[3][0] += a3.z * w.x; acc[3][1] += a3.z * w.y; acc[3][2] += a3.z * w.z; acc[3][3] += a3.z * w.w;
            }
            {
                float4 w = *(const float4*)&W1s[(k + 3) * 128 + j0];
                acc[0][0] += a0.w * w.x; acc[0][1] += a0.w * w.y; acc[0][2] += a0.w * w.z; acc[0][3] += a0.w * w.w;
                acc[1][0] += a1.w * w.x; acc[1][1] += a1.w * w.y; acc[1][2] += a1.w * w.z; acc[1][3] += a1.w * w.w;
                acc[2][0] += a2.w * w.x; acc[2][1] += a2.w * w.y; acc[2][2] += a2.w * w.z; acc[2][3] += a2.w * w.w;
                acc[3][0] += a3.w * w.x; acc[3][1] += a3.w * w.y; acc[3][2] += a3.w * w.z; acc[3][3] += a3.w * w.w;
            }
        }
        __syncthreads();   // all layer-1 reads of in_s[.][128..255] done

        // relu + write hidden into in_s[n][128+j]
        #pragma unroll
        for (int i = 0; i < 4; i++) {
            float4 h;
            h.x = fmaxf(acc[i][0], 0.f);
            h.y = fmaxf(acc[i][1], 0.f);
            h.z = fmaxf(acc[i][2], 0.f);
            h.w = fmaxf(acc[i][3], 0.f);
            *(float4*)&in_s[(n0 + i) * 256 + 128 + j0] = h;
        }
        __syncthreads();

        // ---- layer 2: [32,128] x [128,128] + b2 + residual ------------------
        float4 b2v = *(const float4*)&b2s[j0];
        float acc2[4][4];
        #pragma unroll
        for (int i = 0; i < 4; i++) {
            acc2[i][0] = b2v.x; acc2[i][1] = b2v.y; acc2[i][2] = b2v.z; acc2[i][3] = b2v.w;
        }
        #pragma unroll 4
        for (int k = 0; k < 128; k += 4) {
            float4 a0 = *(const float4*)&in_s[(n0 + 0) * 256 + 128 + k];
            float4 a1 = *(const float4*)&in_s[(n0 + 1) * 256 + 128 + k];
            float4 a2 = *(const float4*)&in_s[(n0 + 2) * 256 + 128 + k];
            float4 a3 = *(const float4*)&in_s[(n0 + 3) * 256 + 128 + k];
            {
                float4 w = *(const float4*)&W2s[(k + 0) * 128 + j0];
                acc2[0][0] += a0.x * w.x; acc2[0][1] += a0.x * w.y; acc2[0][2] += a0.x * w.z; acc2[0][3] += a0.x * w.w;
                acc2[1][0] += a1.x * w.x; acc2[1][1] += a1.x * w.y; acc2[1][2] += a1.x * w.z; acc2[1][3] += a1.x * w.w;
                acc2[2][0] += a2.x * w.x; acc2[2][1] += a2.x * w.y; acc2[2][2] += a2.x * w.z; acc2[2][3] += a2.x * w.w;
                acc2[3][0] += a3.x * w.x; acc2[3][1] += a3.x * w.y; acc2[3][2] += a3.x * w.z; acc2[3][3] += a3.x * w.w;
            }
            {
                float4 w = *(const float4*)&W2s[(k + 1) * 128 + j0];
                acc2[0][0] += a0.y * w.x; acc2[0][1] += a0.y * w.y; acc2[0][2] += a0.y * w.z; acc2[0][3] += a0.y * w.w;
                acc2[1][0] += a1.y * w.x; acc2[1][1] += a1.y * w.y; acc2[1][2] += a1.y * w.z; acc2[1][3] += a1.y * w.w;
                acc2[2][0] += a2.y * w.x; acc2[2][1] += a2.y * w.y; acc2[2][2] += a2.y * w.z; acc2[2][3] += a2.y * w.w;
                acc2[3][0] += a3.y * w.x; acc2[3][1] += a3.y * w.y; acc2[3][2] += a3.y * w.z; acc2[3][3] += a3.y * w.w;
            }
            {
                float4 w = *(const float4*)&W2s[(k + 2) * 128 + j0];
                acc2[0][0] += a0.z * w.x; acc2[0][1] += a0.z * w.y; acc2[0][2] += a0.z * w.z; acc2[0][3] += a0.z * w.w;
                acc2[1][0] += a1.z * w.x; acc2[1][1] += a1.z * w.y; acc2[1][2] += a1.z * w.z; acc2[1][3] += a1.z * w.w;
                acc2[2][0] += a2.z * w.x; acc2[2][1] += a2.z * w.y; acc2[2][2] += a2.z * w.z; acc2[2][3] += a2.z * w.w;
                acc2[3][0] += a3.z * w.x; acc2[3][1] += a3.z * w.y; acc2[3][2] += a3.z * w.z; acc2[3][3] += a3.z * w.w;
            }
            {
                float4 w = *(const float4*)&W2s[(k + 3) * 128 + j0];
                acc2[0][0] += a0.w * w.x; acc2[0][1] += a0.w * w.y; acc2[0][2] += a0.w * w.z; acc2[0][3] += a0.w * w.w;
                acc2[1][0] += a1.w * w.x; acc2[1][1] += a1.w * w.y; acc2[1][2] += a1.w * w.z; acc2[1][3] += a1.w * w.w;
                acc2[2][0] += a2.w * w.x; acc2[2][1] += a2.w * w.y; acc2[2][2] += a2.w * w.z; acc2[2][3] += a2.w * w.w;
                acc2[3][0] += a3.w * w.x; acc2[3][1] += a3.w * w.y; acc2[3][2] += a3.w * w.z; acc2[3][3] += a3.w * w.w;
            }
        }

        // residual (x still intact in in_s[n][0..127]) + store
        #pragma unroll
        for (int i = 0; i < 4; i++) {
            int gnode = tile * MT + n0 + i;
            if (gnode < N_NODES) {
                float4 r = *(const float4*)&in_s[(n0 + i) * 256 + j0];
                float4 o;
                o.x = acc2[i][0] + r.x;
                o.y = acc2[i][1] + r.y;
                o.z = acc2[i][2] + r.z;
                o.w = acc2[i][3] + r.w;
                *(float4*)&out[(size_t)gnode * 128 + j0] = o;
            }
        }
    }
}

// ---------------- launcher ---------------------------------------------------
extern "C" void kernel_launch(void* const* d_in, const int* in_sizes, int n_in,
                              void* d_out, int out_size) {
    const float* x          = (const float*)d_in[0];
    const int*   edge_row   = (const int*)d_in[1];   // int64 downcast; first E = row
    const float* edge_attr  = (const float*)d_in[2];
    const float* W1         = (const float*)d_in[5];
    const float* b1         = (const float*)d_in[6];
    const float* W2         = (const float*)d_in[7];
    const float* b2         = (const float*)d_in[8];
    float*       out        = (float*)d_out;

    zero_counts_kernel<<<(N_NODES + 255) / 256, 256>>>();
    hist_kernel<<<(E_EDGES + 255) / 256, 256>>>(edge_row);
    scan_kernel<<<1, 1024>>>();
    fill_kernel<<<(E_EDGES + 255) / 256, 256>>>(edge_row);
    gather_kernel<<<(N_NODES * 32 + 255) / 256, 256>>>(edge_attr);
    {
        size_t smem_bytes = (32768 + 16384 + 128 + 128 + MT * 256) * sizeof(float);
        cudaFuncSetAttribute(mlp_kernel, cudaFuncAttributeMaxDynamicSharedMemorySize,
                             (int)smem_bytes);
        mlp_kernel<<<148, 256, smem_bytes>>>(x, W1, b1, W2, b2, out);
    }
}

// round 5
// speedup vs baseline: 2.9918x; 1.3621x over previous
#include <cuda_runtime.h>
#include <cuda_bf16.h>
#include <cstdint>

#define N_NODES 50000
#define E_EDGES 625000
#define HIDDEN  128

// ---------------- scratch ----------------------------------------------------
__device__ float g_sum[N_NODES * HIDDEN];
__device__ int   g_count[N_NODES];
__device__ int   g_offset[N_NODES];
__device__ int   g_cursor[N_NODES];
__device__ int   g_edge_ids[E_EDGES];

// ---------------- 1..5: CSR build + gather (validated) -----------------------
__global__ void zero_counts_kernel() {
    int i = blockIdx.x * blockDim.x + threadIdx.x;
    if (i < N_NODES) g_count[i] = 0;
}
__global__ void hist_kernel(const int* __restrict__ edge_row) {
    int e = blockIdx.x * blockDim.x + threadIdx.x;
    if (e < E_EDGES) atomicAdd(&g_count[edge_row[e]], 1);
}
__global__ void scan_kernel() {
    __shared__ int s[1024];
    const int t = threadIdx.x;
    const int CHUNK = (N_NODES + 1023) / 1024;
    int base = t * CHUNK;
    int sum = 0;
    for (int i = 0; i < CHUNK; i++) {
        int idx = base + i;
        if (idx < N_NODES) sum += g_count[idx];
    }
    s[t] = sum;
    __syncthreads();
    for (int off = 1; off < 1024; off <<= 1) {
        int v = 0;
        if (t >= off) v = s[t - off];
        __syncthreads();
        if (t >= off) s[t] += v;
        __syncthreads();
    }
    int run = (t == 0) ? 0 : s[t - 1];
    for (int i = 0; i < CHUNK; i++) {
        int idx = base + i;
        if (idx < N_NODES) {
            g_offset[idx] = run;
            g_cursor[idx] = run;
            run += g_count[idx];
        }
    }
}
__global__ void fill_kernel(const int* __restrict__ edge_row) {
    int e = blockIdx.x * blockDim.x + threadIdx.x;
    if (e < E_EDGES) {
        int pos = atomicAdd(&g_cursor[edge_row[e]], 1);
        g_edge_ids[pos] = e;
    }
}
__global__ void gather_kernel(const float* __restrict__ edge_attr) {
    int gtid = blockIdx.x * blockDim.x + threadIdx.x;
    int warp = gtid >> 5;
    int lane = gtid & 31;
    if (warp >= N_NODES) return;
    int start = g_offset[warp];
    int cnt   = g_count[warp];
    float4 acc = make_float4(0.f, 0.f, 0.f, 0.f);
    const float4* ea4 = (const float4*)edge_attr;
    int i = 0;
    for (; i + 4 <= cnt; i += 4) {
        int e0 = g_edge_ids[start + i + 0];
        int e1 = g_edge_ids[start + i + 1];
        int e2 = g_edge_ids[start + i + 2];
        int e3 = g_edge_ids[start + i + 3];
        float4 v0 = ea4[(size_t)e0 * 32 + lane];
        float4 v1 = ea4[(size_t)e1 * 32 + lane];
        float4 v2 = ea4[(size_t)e2 * 32 + lane];
        float4 v3 = ea4[(size_t)e3 * 32 + lane];
        acc.x += v0.x + v1.x + v2.x + v3.x;
        acc.y += v0.y + v1.y + v2.y + v3.y;
        acc.z += v0.z + v1.z + v2.z + v3.z;
        acc.w += v0.w + v1.w + v2.w + v3.w;
    }
    for (; i < cnt; i++) {
        int e = g_edge_ids[start + i];
        float4 v = ea4[(size_t)e * 32 + lane];
        acc.x += v.x; acc.y += v.y; acc.z += v.z; acc.w += v.w;
    }
    ((float4*)g_sum)[(size_t)warp * 32 + lane] = acc;
}

// ---------------- 6. MLP via mma.sync (HMMA fallback path, no 'a' features) --
// D[128n,128j] per tile. 8 warps x m16 rows. bf16 split precision, 3 passes.
// A frags: gmem fp32 -> in-register split. B frags: W^T hi/lo staged in smem.
// Layer-1 accumulators re-used directly as layer-2 A frags (same lane layout).

__device__ __forceinline__ void mma_bf16(float4& d,
    uint32_t a0, uint32_t a1, uint32_t a2, uint32_t a3,
    uint32_t b0, uint32_t b1) {
    asm volatile(
        "mma.sync.aligned.m16n8k16.row.col.f32.bf16.bf16.f32 "
        "{%0,%1,%2,%3}, {%4,%5,%6,%7}, {%8,%9}, {%0,%1,%2,%3};"
        : "+f"(d.x), "+f"(d.y), "+f"(d.z), "+f"(d.w)
        : "r"(a0), "r"(a1), "r"(a2), "r"(a3), "r"(b0), "r"(b1));
}
__device__ __forceinline__ void split2(float a, float b, uint32_t& hi, uint32_t& lo) {
    __nv_bfloat16 ha = __float2bfloat16_rn(a);
    __nv_bfloat16 hb = __float2bfloat16_rn(b);
    __nv_bfloat162 H; H.x = ha; H.y = hb;
    hi = *(uint32_t*)&H;
    __nv_bfloat162 L;
    L.x = __float2bfloat16_rn(a - __bfloat162float(ha));
    L.y = __float2bfloat16_rn(b - __bfloat162float(hb));
    lo = *(uint32_t*)&L;
}

#define TILE_M  128
#define N_TILES ((N_NODES + TILE_M - 1) / TILE_M)   // 391
#define KS1 264   // W1^T row stride (256 k + 8 pad) -> conflict-free B LDS
#define KS2 136   // W2^T row stride (128 k + 8 pad)
// smem: W1Th | W1Tl | W2Th | W2Tl | b1s | b2s
#define MLP_SMEM (128*KS1*2*2 + 128*KS2*2*2 + 256*4)   // 205824 B

__global__ __launch_bounds__(256, 1)
void mlp_mma_kernel(const float* __restrict__ x,
                    const float* __restrict__ W1, const float* __restrict__ b1,
                    const float* __restrict__ W2, const float* __restrict__ b2,
                    float* __restrict__ out) {
    extern __shared__ char smem[];
    __nv_bfloat16* W1Th = (__nv_bfloat16*)smem;
    __nv_bfloat16* W1Tl = W1Th + 128 * KS1;
    __nv_bfloat16* W2Th = W1Tl + 128 * KS1;
    __nv_bfloat16* W2Tl = W2Th + 128 * KS2;
    float* b1s = (float*)(W2Tl + 128 * KS2);
    float* b2s = b1s + 128;

    const int tid = threadIdx.x;

    // ---- stage weights transposed + split (once per CTA) ----
    for (int i = tid; i < 256 * 128; i += 256) {
        int k = i >> 7, j = i & 127;
        float v = W1[i];
        __nv_bfloat16 h = __float2bfloat16_rn(v);
        W1Th[j * KS1 + k] = h;
        W1Tl[j * KS1 + k] = __float2bfloat16_rn(v - __bfloat162float(h));
    }
    for (int i = tid; i < 128 * 128; i += 256) {
        int k = i >> 7, j = i & 127;
        float v = W2[i];
        __nv_bfloat16 h = __float2bfloat16_rn(v);
        W2Th[j * KS2 + k] = h;
        W2Tl[j * KS2 + k] = __float2bfloat16_rn(v - __bfloat162float(h));
    }
    if (tid < 128) { b1s[tid] = b1[tid]; b2s[tid] = b2[tid]; }
    __syncthreads();
    // no further __syncthreads needed: warps are fully independent below

    const int w    = tid >> 5;
    const int lane = tid & 31;
    const int p    = lane >> 2;   // row-in-group / B n-index
    const int q    = lane & 3;    // k-quad / col pair

    for (int tile = blockIdx.x; tile < N_TILES; tile += gridDim.x) {
        const int row0 = tile * TILE_M + w * 16 + p;
        const int row1 = row0 + 8;
        const bool ok0 = row0 < N_NODES;
        const bool ok1 = row1 < N_NODES;
        const float* xr0 = x + (size_t)row0 * 128;
        const float* xr1 = x + (size_t)row1 * 128;
        const float* sr0 = g_sum + (size_t)row0 * 128;
        const float* sr1 = g_sum + (size_t)row1 * 128;

        // ---- layer 1: k = 256 (16 steps), 16 n-frags ----
        float4 acc[16];
        #pragma unroll
        for (int nf = 0; nf < 16; nf++) acc[nf] = make_float4(0.f, 0.f, 0.f, 0.f);

        #pragma unroll
        for (int ks = 0; ks < 16; ks++) {
            const float* p0 = (ks < 8) ? xr0 : sr0;
            const float* p1 = (ks < 8) ? xr1 : sr1;
            const int ko = (ks & 7) * 16 + q * 2;      // offset within x / g_sum
            float2 v00 = ok0 ? *(const float2*)(p0 + ko)     : make_float2(0.f, 0.f);
            float2 v01 = ok0 ? *(const float2*)(p0 + ko + 8) : make_float2(0.f, 0.f);
            float2 v10 = ok1 ? *(const float2*)(p1 + ko)     : make_float2(0.f, 0.f);
            float2 v11 = ok1 ? *(const float2*)(p1 + ko + 8) : make_float2(0.f, 0.f);
            uint32_t a0h, a0l, a1h, a1l, a2h, a2l, a3h, a3l;
            split2(v00.x, v00.y, a0h, a0l);
            split2(v10.x, v10.y, a1h, a1l);
            split2(v01.x, v01.y, a2h, a2l);
            split2(v11.x, v11.y, a3h, a3l);
            const int kb = ks * 16 + q * 2;            // weight k index
            #pragma unroll
            for (int nf = 0; nf < 16; nf++) {
                const int j = nf * 8 + p;
                uint32_t b0h = *(const uint32_t*)&W1Th[j * KS1 + kb];
                uint32_t b1h = *(const uint32_t*)&W1Th[j * KS1 + kb + 8];
                uint32_t b0l = *(const uint32_t*)&W1Tl[j * KS1 + kb];
                uint32_t b1l = *(const uint32_t*)&W1Tl[j * KS1 + kb + 8];
                mma_bf16(acc[nf], a0h, a1h, a2h, a3h, b0h, b1h);
                mma_bf16(acc[nf], a0h, a1h, a2h, a3h, b0l, b1l);
                mma_bf16(acc[nf], a0l, a1l, a2l, a3l, b0h, b1h);
            }
        }

        // ---- bias + relu + split: acc -> layer-2 A frags (in-register) ----
        uint32_t ah[8][4], al[8][4];
        #pragma unroll
        for (int ks2 = 0; ks2 < 8; ks2++) {
            #pragma unroll
            for (int half = 0; half < 2; half++) {
                const int nf = ks2 * 2 + half;
                float2 bv = *(const float2*)&b1s[nf * 8 + q * 2];
                float hx = fmaxf(acc[nf].x + bv.x, 0.f);
                float hy = fmaxf(acc[nf].y + bv.y, 0.f);
                float hz = fmaxf(acc[nf].z + bv.x, 0.f);
                float hw = fmaxf(acc[nf].w + bv.y, 0.f);
                split2(hx, hy, ah[ks2][half * 2 + 0], al[ks2][half * 2 + 0]);
                split2(hz, hw, ah[ks2][half * 2 + 1], al[ks2][half * 2 + 1]);
            }
        }

        // ---- layer 2: k = 128 (8 steps), 16 n-frags ----
        float4 acc2[16];
        #pragma unroll
        for (int nf = 0; nf < 16; nf++) acc2[nf] = make_float4(0.f, 0.f, 0.f, 0.f);

        #pragma unroll
        for (int ks2 = 0; ks2 < 8; ks2++) {
            const int kb = ks2 * 16 + q * 2;
            #pragma unroll
            for (int nf = 0; nf < 16; nf++) {
                const int j = nf * 8 + p;
                uint32_t b0h = *(const uint32_t*)&W2Th[j * KS2 + kb];
                uint32_t b1h = *(const uint32_t*)&W2Th[j * KS2 + kb + 8];
                uint32_t b0l = *(const uint32_t*)&W2Tl[j * KS2 + kb];
                uint32_t b1l = *(const uint32_t*)&W2Tl[j * KS2 + kb + 8];
                mma_bf16(acc2[nf], ah[ks2][0], ah[ks2][1], ah[ks2][2], ah[ks2][3], b0h, b1h);
                mma_bf16(acc2[nf], ah[ks2][0], ah[ks2][1], ah[ks2][2], ah[ks2][3], b0l, b1l);
                mma_bf16(acc2[nf], al[ks2][0], al[ks2][1], al[ks2][2], al[ks2][3], b0h, b1h);
            }
        }

        // ---- epilogue: + b2 + residual, store ----
        #pragma unroll
        for (int nf = 0; nf < 16; nf++) {
            const int j = nf * 8 + q * 2;
            float2 bv = *(const float2*)&b2s[j];
            if (ok0) {
                float2 xr = *(const float2*)(xr0 + j);
                float2 o;
                o.x = acc2[nf].x + bv.x + xr.x;
                o.y = acc2[nf].y + bv.y + xr.y;
                *(float2*)(out + (size_t)row0 * 128 + j) = o;
            }
            if (ok1) {
                float2 xr = *(const float2*)(xr1 + j);
                float2 o;
                o.x = acc2[nf].z + bv.x + xr.x;
                o.y = acc2[nf].w + bv.y + xr.y;
                *(float2*)(out + (size_t)row1 * 128 + j) = o;
            }
        }
    }
}

// ---------------- launcher ---------------------------------------------------
extern "C" void kernel_launch(void* const* d_in, const int* in_sizes, int n_in,
                              void* d_out, int out_size) {
    const float* x          = (const float*)d_in[0];
    const int*   edge_row   = (const int*)d_in[1];   // int64 downcast; first E = row
    const float* edge_attr  = (const float*)d_in[2];
    const float* W1         = (const float*)d_in[5];
    const float* b1         = (const float*)d_in[6];
    const float* W2         = (const float*)d_in[7];
    const float* b2         = (const float*)d_in[8];
    float*       out        = (float*)d_out;

    zero_counts_kernel<<<(N_NODES + 255) / 256, 256>>>();
    hist_kernel<<<(E_EDGES + 255) / 256, 256>>>(edge_row);
    scan_kernel<<<1, 1024>>>();
    fill_kernel<<<(E_EDGES + 255) / 256, 256>>>(edge_row);
    gather_kernel<<<(N_NODES * 32 + 255) / 256, 256>>>(edge_attr);

    cudaFuncSetAttribute(mlp_mma_kernel, cudaFuncAttributeMaxDynamicSharedMemorySize, MLP_SMEM);
    mlp_mma_kernel<<<148, 256, MLP_SMEM>>>(x, W1, b1, W2, b2, out);
}